// round 3
// baseline (speedup 1.0000x reference)
#include <cuda_runtime.h>

#define NSIDE    48
#define NPIX     2304          // 48*48
#define NTHREADS 192           // 16 p-groups(3) x 12 x-groups(4)
#define NWARPS   6
#define EPS_F    0.01f
#define INV_EPS  100.0f
#define MAXB     64

__device__ float g_cost[MAXB];

// ---------------------------------------------------------------------------
// block reduce (all threads receive the sum; deterministic order)
// ---------------------------------------------------------------------------
__device__ __forceinline__ float block_reduce(float val, float* red) {
#pragma unroll
    for (int o = 16; o; o >>= 1) val += __shfl_down_sync(0xffffffffu, val, o);
    if ((threadIdx.x & 31) == 0) red[threadIdx.x >> 5] = val;
    __syncthreads();
    float s = red[0];
#pragma unroll
    for (int w = 1; w < NWARPS; w++) s += red[w];
    __syncthreads();   // red reusable after return
    return s;
}

// ---------------------------------------------------------------------------
// 48x48 matmul: dst = A * B, where A and/or B may be the |i-j| Gaussian table.
// MODE: 0 = dense smem matrix, 1 = Ktab (exp(-d^2/eps)), 2 = KDtab (K*d^2).
// Thread tile: 3 rows x 4 cols (192 threads cover all 2304 outputs).
// ---------------------------------------------------------------------------
template <int AM, int BM>
__device__ __forceinline__ void mm48(float* __restrict__ dst,
                                     const float* __restrict__ A,
                                     const float* __restrict__ B,
                                     const float* __restrict__ ktab,
                                     const float* __restrict__ kdtab) {
    const int t  = threadIdx.x;
    const int a0 = (t / 12) * 3;
    const int c0 = (t % 12) * 4;

    float acc[3][4];
#pragma unroll
    for (int i = 0; i < 3; i++)
#pragma unroll
        for (int j = 0; j < 4; j++) acc[i][j] = 0.0f;

#pragma unroll 4
    for (int b = 0; b < 48; b++) {
        float av[3];
#pragma unroll
        for (int i = 0; i < 3; i++) {
            if constexpr (AM == 0) {
                av[i] = A[(a0 + i) * 48 + b];
            } else {
                int d = a0 + i - b; d = d < 0 ? -d : d;
                av[i] = (AM == 1 ? ktab : kdtab)[d];
            }
        }
        float bv[4];
        if constexpr (BM == 0) {
            float4 v4 = *reinterpret_cast<const float4*>(&B[b * 48 + c0]);
            bv[0] = v4.x; bv[1] = v4.y; bv[2] = v4.z; bv[3] = v4.w;
        } else {
#pragma unroll
            for (int j = 0; j < 4; j++) {
                int d = b - (c0 + j); d = d < 0 ? -d : d;
                bv[j] = (BM == 1 ? ktab : kdtab)[d];
            }
        }
#pragma unroll
        for (int i = 0; i < 3; i++)
#pragma unroll
            for (int j = 0; j < 4; j++)
                acc[i][j] = fmaf(av[i], bv[j], acc[i][j]);
    }

#pragma unroll
    for (int i = 0; i < 3; i++) {
        float4 o;
        o.x = acc[i][0]; o.y = acc[i][1]; o.z = acc[i][2]; o.w = acc[i][3];
        *reinterpret_cast<float4*>(&dst[(a0 + i) * 48 + c0]) = o;
    }
}

__device__ __forceinline__ float mass_of(float x) {
    return fminf(fmaxf(x, 0.0f), 1e9f) + 1e-9f;
}

// ---------------------------------------------------------------------------
// One CTA per batch image. Full Sinkhorn in shared memory via separable
// Gaussian kernel transforms.
// ---------------------------------------------------------------------------
__global__ __launch_bounds__(NTHREADS)
void sinkhorn_kernel(const float* __restrict__ y, const float* __restrict__ yt) {
    __shared__ __align__(16) float sW[NPIX];   // work / e^{v/eps} or e^{u/eps}
    __shared__ __align__(16) float sT[NPIX];   // row-transform temp
    __shared__ __align__(16) float sU[NPIX];   // potential u
    __shared__ __align__(16) float sV[NPIX];   // potential v (reused as Sf at end)
    __shared__ float ktab[NSIDE];
    __shared__ float kdtab[NSIDE];
    __shared__ float red[NWARPS];

    const int tid = threadIdx.x;
    const float* yb  = y  + (size_t)blockIdx.x * NPIX;
    const float* ytb = yt + (size_t)blockIdx.x * NPIX;

    // Gaussian tables: k(d) = exp(-(d/48)^2/eps), kd(d) = k(d)*(d/48)^2
    for (int d = tid; d < NSIDE; d += NTHREADS) {
        float dd = (float)d / 48.0f;
        float d2 = dd * dd;
        float k  = expf(-d2 * INV_EPS);
        ktab[d]  = k;
        kdtab[d] = k * d2;
    }

    // mass sums; init potentials
    float sxl = 0.0f, syl = 0.0f;
    for (int i = tid; i < NPIX; i += NTHREADS) {
        sxl += mass_of(yb[i]);
        syl += mass_of(ytb[i]);
        sU[i] = 0.0f;
        sV[i] = 0.0f;
    }
    __syncthreads();
    const float sx = block_reduce(sxl, red);
    const float sy = block_reduce(syl, red);

    // 5 Sinkhorn iterations (lse via separable kernel, non-shifted + 1e-6)
    for (int it = 0; it < 5; it++) {
        // u update: rowsum_i = e^{u_i/eps} * (K * e^{v/eps} * K)_i
        for (int i = tid; i < NPIX; i += NTHREADS) sW[i] = expf(sV[i] * INV_EPS);
        __syncthreads();
        mm48<1, 0>(sT, nullptr, sW, ktab, kdtab);   // T = K * W   (y axis)
        __syncthreads();
        mm48<0, 1>(sW, sT, nullptr, ktab, kdtab);   // W = T * K   (x axis)
        __syncthreads();
        for (int i = tid; i < NPIX; i += NTHREADS) {
            float lmu = logf(mass_of(yb[i]) / sx);
            float t   = expf(sU[i] * INV_EPS) * sW[i];
            sU[i] = EPS_F * (lmu - logf(t + 1e-6f)) + sU[i];
        }
        __syncthreads();

        // v update (uses updated u)
        for (int i = tid; i < NPIX; i += NTHREADS) sW[i] = expf(sU[i] * INV_EPS);
        __syncthreads();
        mm48<1, 0>(sT, nullptr, sW, ktab, kdtab);
        __syncthreads();
        mm48<0, 1>(sW, sT, nullptr, ktab, kdtab);
        __syncthreads();
        for (int i = tid; i < NPIX; i += NTHREADS) {
            float lnu = logf(mass_of(ytb[i]) / sy);
            float t   = expf(sV[i] * INV_EPS) * sW[i];
            sV[i] = EPS_F * (lnu - logf(t + 1e-6f)) + sV[i];
        }
        __syncthreads();
    }

    // cost = a^T (KD B K) b-part + a^T (K B KD) b-part, a=e^{u/eps}, B=e^{v/eps}
    for (int i = tid; i < NPIX; i += NTHREADS) sW[i] = expf(sV[i] * INV_EPS);
    __syncthreads();

    float cl = 0.0f;

    mm48<2, 0>(sT, nullptr, sW, ktab, kdtab);       // T  = KD * B
    __syncthreads();
    mm48<0, 1>(sV, sT, nullptr, ktab, kdtab);       // Sf = T * K   (sV reused)
    __syncthreads();
    for (int i = tid; i < NPIX; i += NTHREADS)
        cl += expf(sU[i] * INV_EPS) * sV[i];
    __syncthreads();

    mm48<1, 0>(sT, nullptr, sW, ktab, kdtab);       // T  = K * B
    __syncthreads();
    mm48<0, 2>(sV, sT, nullptr, ktab, kdtab);       // Sf = T * KD
    __syncthreads();
    for (int i = tid; i < NPIX; i += NTHREADS)
        cl += expf(sU[i] * INV_EPS) * sV[i];
    __syncthreads();

    float c = block_reduce(cl, red);
    if (tid == 0) g_cost[blockIdx.x] = c;
}

__global__ void finalize_kernel(float* __restrict__ out, int nb) {
    float s = 0.0f;
    for (int i = 0; i < nb; i++) s += g_cost[i];
    *out = s / (float)nb;
}

extern "C" void kernel_launch(void* const* d_in, const int* in_sizes, int n_in,
                              void* d_out, int out_size) {
    const float* y  = (const float*)d_in[0];
    const float* yt = (const float*)d_in[1];
    float* out = (float*)d_out;

    int nb = in_sizes[0] / NPIX;           // 16
    if (nb < 1) nb = 1;
    if (nb > MAXB) nb = MAXB;

    sinkhorn_kernel<<<nb, NTHREADS>>>(y, yt);
    finalize_kernel<<<1, 1>>>(out, nb);
}